// round 9
// baseline (speedup 1.0000x reference)
#include <cuda_runtime.h>

// B=4, L=2048, H=8, D=64, M=256, chunk T=128, 16 chunks/head
#define NRMc   0.35355339059327373f   // 64^-0.25
#define RATIOc 0.0625f                // 1/sqrt(256)
#define KEPSc  1e-4f

__device__ float g_qp[16777216];   // [65536][256] query features
__device__ float g_kp[16777216];   // [65536][256] key dash -> features (in place)
__device__ float g_kv[8388608];    // [512][256][64] block KV -> exclusive prefix
__device__ float g_s[131072];      // [512][256]    block k-sums -> exclusive prefix
__device__ float g_kmax[32];

__device__ __forceinline__ void atomicMaxFloat(float* addr, float v) {
    if (v >= 0.f) atomicMax((int*)addr, __float_as_int(v));
    else          atomicMin((unsigned int*)addr, __float_as_uint(v));
}

__global__ void k_init() {
    if (threadIdx.x < 32) g_kmax[threadIdx.x] = __int_as_float(0xff800000);
}

// ---------------- 3xTF32 MMA helpers; smem holds interleaved (hi,lo) float2 --
__device__ __forceinline__ float2 tfsplit(float x) {
    unsigned h; asm("cvt.rna.tf32.f32 %0, %1;" : "=r"(h) : "f"(x));
    float hf = __uint_as_float(h);
    float r = x - hf;
    unsigned l; asm("cvt.rna.tf32.f32 %0, %1;" : "=r"(l) : "f"(r));
    return make_float2(hf, __uint_as_float(l));
}
struct FA { unsigned h[4]; unsigned l[4]; };
struct FB { unsigned h[2]; unsigned l[2]; };

__device__ __forceinline__ void mma8(float c[4], const unsigned a[4], const unsigned b[2]) {
    asm volatile("mma.sync.aligned.m16n8k8.row.col.f32.tf32.tf32.f32 "
                 "{%0,%1,%2,%3},{%4,%5,%6,%7},{%8,%9},{%0,%1,%2,%3};"
                 : "+f"(c[0]), "+f"(c[1]), "+f"(c[2]), "+f"(c[3])
                 : "r"(a[0]), "r"(a[1]), "r"(a[2]), "r"(a[3]), "r"(b[0]), "r"(b[1]));
}
__device__ __forceinline__ void mma3(float c[4], const FA& a, const FB& b) {
    mma8(c, a.l, b.h);
    mma8(c, a.h, b.l);
    mma8(c, a.h, b.h);
}
// A[r][k] fragment from interleaved row-major S[r][k] (pitch P float2)
__device__ __forceinline__ void lda2(FA& a, const float2* S, int P, int r, int k, int g, int t) {
    float2 v0 = S[(r+g)*P + k + t];
    float2 v1 = S[(r+g+8)*P + k + t];
    float2 v2 = S[(r+g)*P + k + t + 4];
    float2 v3 = S[(r+g+8)*P + k + t + 4];
    a.h[0] = __float_as_uint(v0.x); a.l[0] = __float_as_uint(v0.y);
    a.h[1] = __float_as_uint(v1.x); a.l[1] = __float_as_uint(v1.y);
    a.h[2] = __float_as_uint(v2.x); a.l[2] = __float_as_uint(v2.y);
    a.h[3] = __float_as_uint(v3.x); a.l[3] = __float_as_uint(v3.y);
}
// A[m][k] fragment from interleaved S stored [k][m] (pitch P float2)
__device__ __forceinline__ void lda2_t(FA& a, const float2* S, int P, int r, int k, int g, int t) {
    float2 v0 = S[(k+t)*P + r + g];
    float2 v1 = S[(k+t)*P + r + g + 8];
    float2 v2 = S[(k+t+4)*P + r + g];
    float2 v3 = S[(k+t+4)*P + r + g + 8];
    a.h[0] = __float_as_uint(v0.x); a.l[0] = __float_as_uint(v0.y);
    a.h[1] = __float_as_uint(v1.x); a.l[1] = __float_as_uint(v1.y);
    a.h[2] = __float_as_uint(v2.x); a.l[2] = __float_as_uint(v2.y);
    a.h[3] = __float_as_uint(v3.x); a.l[3] = __float_as_uint(v3.y);
}
// B[k][n] fragment from interleaved S stored [n][k] (pitch P float2)
__device__ __forceinline__ void ldb2_nk(FB& b, const float2* S, int P, int n, int k, int g, int t) {
    float2 v0 = S[(n+g)*P + k + t];
    float2 v1 = S[(n+g)*P + k + t + 4];
    b.h[0] = __float_as_uint(v0.x); b.l[0] = __float_as_uint(v0.y);
    b.h[1] = __float_as_uint(v1.x); b.l[1] = __float_as_uint(v1.y);
}
// B[k][n] fragment from interleaved S stored [k][n] (pitch P float2)
__device__ __forceinline__ void ldb2_kn(FB& b, const float2* S, int P, int k, int n, int g, int t) {
    float2 v0 = S[(k+t)*P + n + g];
    float2 v1 = S[(k+t+4)*P + n + g];
    b.h[0] = __float_as_uint(v0.x); b.l[0] = __float_as_uint(v0.y);
    b.h[1] = __float_as_uint(v1.x); b.l[1] = __float_as_uint(v1.y);
}
// write 4 consecutive split elements as two float4 (16B STS each)
__device__ __forceinline__ void st_split4(float2* dst, float4 x) {
    float2 s0 = tfsplit(x.x), s1 = tfsplit(x.y), s2 = tfsplit(x.z), s3 = tfsplit(x.w);
    *(float4*)&dst[0] = make_float4(s0.x, s0.y, s1.x, s1.y);
    *(float4*)&dst[2] = make_float4(s2.x, s2.y, s3.x, s3.y);
}
// write exactly 2 consecutive split elements (one 16B STS) — for 2-col ownership
__device__ __forceinline__ void st_split2(float2* dst, float a0, float a1) {
    float2 s0 = tfsplit(a0), s1 = tfsplit(a1);
    *(float4*)&dst[0] = make_float4(s0.x, s0.y, s1.x, s1.y);
}

// ---------------------------------------------------------------------------
// Features: dash[64x256] = (NRM*X)[64x64] @ P^T. 512 thr, 16 warps (2x8).
// smem 174KB: X and proj both pre-split interleaved.
// ---------------------------------------------------------------------------
__global__ __launch_bounds__(512) void k_feat(const float* __restrict__ x,
                                              const float* __restrict__ proj,
                                              int is_query) {
    extern __shared__ float sm[];
    float2* qhl = (float2*)sm;            // [64][68] f2
    float2* phl = (float2*)(sm + 8704);   // [256][68] f2
    float*  dash = sm + 8704;             // alias after GEMM: [64][257] fp32
    __shared__ float rmax_s[64];
    __shared__ float diag_s[64];
    __shared__ float pmax[512];

    int tid = threadIdx.x, lane = tid & 31, wid = tid >> 5;
    int g = lane >> 2, t = lane & 3;
    int wr = wid >> 3, wc = wid & 7;       // 2 x 8 warps: 32 rows x 32 cols
    int n0 = blockIdx.x * 64;
    float* outp = is_query ? g_qp : g_kp;

    for (int idx = tid; idx < 1024; idx += 512) {        // X: scale + split
        int r = idx >> 4, d4 = idx & 15;
        float4 v = *(const float4*)&x[(size_t)(n0 + r) * 64 + d4 * 4];
        v.x *= NRMc; v.y *= NRMc; v.z *= NRMc; v.w *= NRMc;
        st_split4(&qhl[r*68 + d4*4], v);
    }
    for (int idx = tid; idx < 4096; idx += 512) {        // proj: split
        int m = idx >> 4, d4 = idx & 15;
        st_split4(&phl[m*68 + d4*4], *(const float4*)&proj[(size_t)m * 64 + d4 * 4]);
    }
    __syncthreads();

    if (tid < 64) {      // diag = 0.5*||NRM*x||^2 (h+l reconstruct)
        float ssum = 0.f;
        #pragma unroll
        for (int i = 0; i < 64; i++) {
            float2 hl = qhl[tid*68 + i];
            float a = hl.x + hl.y;
            ssum += a*a;
        }
        diag_s[tid] = 0.5f * ssum;
    }

    float C[2][4][4];
    #pragma unroll
    for (int mt = 0; mt < 2; mt++)
        #pragma unroll
        for (int nt = 0; nt < 4; nt++)
            #pragma unroll
            for (int i = 0; i < 4; i++) C[mt][nt][i] = 0.f;

    #pragma unroll 1
    for (int k0 = 0; k0 < 64; k0 += 8) {
        FA a[2]; FB b[4];
        #pragma unroll
        for (int mt = 0; mt < 2; mt++) lda2(a[mt], qhl, 68, wr*32 + mt*16, k0, g, t);
        #pragma unroll
        for (int nt = 0; nt < 4; nt++) ldb2_nk(b[nt], phl, 68, wc*32 + nt*8, k0, g, t);
        #pragma unroll
        for (int mt = 0; mt < 2; mt++)
            #pragma unroll
            for (int nt = 0; nt < 4; nt++) mma3(C[mt][nt], a[mt], b[nt]);
    }
    __syncthreads();   // phl reads done; alias as dash

    #pragma unroll
    for (int mt = 0; mt < 2; mt++)
        #pragma unroll
        for (int nt = 0; nt < 4; nt++) {
            int r = wr*32 + mt*16 + g, c = wc*32 + nt*8 + 2*t;
            dash[r*257 + c]       = C[mt][nt][0];
            dash[r*257 + c + 1]   = C[mt][nt][1];
            dash[(r+8)*257 + c]   = C[mt][nt][2];
            dash[(r+8)*257 + c+1] = C[mt][nt][3];
        }
    __syncthreads();

    {   // row max: 8 threads per row, staggered
        int row = tid >> 3, part = tid & 7;
        float mx = __int_as_float(0xff800000);
        const float* dr = &dash[row*257 + part*32];
        #pragma unroll 4
        for (int i = 0; i < 32; i++) {
            int ii = (i + part*4) & 31;
            mx = fmaxf(mx, dr[ii]);
        }
        pmax[tid] = mx;
    }
    __syncthreads();
    if (tid < 64) {
        float mx = pmax[tid*8];
        #pragma unroll
        for (int p = 1; p < 8; p++) mx = fmaxf(mx, pmax[tid*8 + p]);
        rmax_s[tid] = mx;
        if (!is_query) {
            int n = n0 + tid;
            atomicMaxFloat(&g_kmax[((n >> 14) << 3) | (n & 7)], mx);
        }
    }
    __syncthreads();

    int m = tid & 255, rh = tid >> 8;
    #pragma unroll 1
    for (int r = rh*32; r < rh*32 + 32; r++) {
        float val = dash[r*257 + m] - diag_s[r];
        if (is_query) val = RATIOc * (expf(val - rmax_s[r]) + KEPSc);
        outp[(size_t)(n0 + r) * 256 + m] = val;
    }
}

// ---------------------------------------------------------------------------
// Per-chunk KV[256x64] = Kp^T @ V, S[256] = colsum(Kp). Fused key exp.
// 512 thr, 16 warps (4x4). grid = 512.
// ---------------------------------------------------------------------------
__global__ __launch_bounds__(512) void k_kvblk(const float* __restrict__ v) {
    extern __shared__ float sm[];
    float2* kphl = (float2*)sm;             // [32][260] f2
    float2* vhl  = (float2*)(sm + 16640);   // [32][68] f2
    __shared__ float ssum2[512];

    int tid = threadIdx.x, lane = tid & 31, wid = tid >> 5;
    int g = lane >> 2, t = lane & 3;
    int wr = wid >> 2, wc = wid & 3;     // 4 x 4 warps
    int bh = blockIdx.x >> 4, j = blockIdx.x & 15;
    int b = bh >> 3, h = bh & 7;
    size_t rowbase = (size_t)(b * 2048 + j * 128) * 8 + h;
    float st = g_kmax[bh];

    float C[4][2][4];
    #pragma unroll
    for (int mt = 0; mt < 4; mt++)
        #pragma unroll
        for (int nt = 0; nt < 2; nt++)
            #pragma unroll
            for (int i = 0; i < 4; i++) C[mt][nt][i] = 0.f;
    float ssum = 0.f;
    int scol = tid & 255, uh = tid >> 8;   // 2 threads per column

    #pragma unroll 1
    for (int uc = 0; uc < 4; uc++) {
        __syncthreads();
        for (int idx = tid; idx < 2048; idx += 512) {   // kp: exp + writeback + split
            int u = idx >> 6, m4 = idx & 63;
            size_t gaddr = (rowbase + (size_t)(uc*32 + u) * 8) * 256 + m4*4;
            float4 x = *(const float4*)&g_kp[gaddr];
            x.x = RATIOc * (expf(x.x - st) + KEPSc);
            x.y = RATIOc * (expf(x.y - st) + KEPSc);
            x.z = RATIOc * (expf(x.z - st) + KEPSc);
            x.w = RATIOc * (expf(x.w - st) + KEPSc);
            *(float4*)&g_kp[gaddr] = x;
            st_split4(&kphl[u*260 + m4*4], x);
        }
        for (int idx = tid; idx < 512; idx += 512) {    // v: split
            int u = idx >> 4, d4 = idx & 15;
            st_split4(&vhl[u*68 + d4*4],
                      *(const float4*)&v[(rowbase + (size_t)(uc*32 + u) * 8) * 64 + d4*4]);
        }
        __syncthreads();

        #pragma unroll
        for (int u = uh*16; u < uh*16 + 16; u++) {
            float2 hl = kphl[u*260 + scol];
            ssum += hl.x + hl.y;
        }

        #pragma unroll
        for (int k0 = 0; k0 < 32; k0 += 8) {
            FA a[4]; FB bv[2];
            #pragma unroll
            for (int mt = 0; mt < 4; mt++) lda2_t(a[mt], kphl, 260, wr*64 + mt*16, k0, g, t);
            #pragma unroll
            for (int nt = 0; nt < 2; nt++) ldb2_kn(bv[nt], vhl, 68, k0, wc*16 + nt*8, g, t);
            #pragma unroll
            for (int mt = 0; mt < 4; mt++)
                #pragma unroll
                for (int nt = 0; nt < 2; nt++) mma3(C[mt][nt], a[mt], bv[nt]);
        }
    }

    float* o = &g_kv[(size_t)blockIdx.x * 16384];
    #pragma unroll
    for (int mt = 0; mt < 4; mt++)
        #pragma unroll
        for (int nt = 0; nt < 2; nt++) {
            int m = wr*64 + mt*16 + g, d = wc*16 + nt*8 + 2*t;
            *(float2*)&o[m*64 + d]     = make_float2(C[mt][nt][0], C[mt][nt][1]);
            *(float2*)&o[(m+8)*64 + d] = make_float2(C[mt][nt][2], C[mt][nt][3]);
        }
    ssum2[tid] = ssum;
    __syncthreads();
    if (tid < 256) g_s[blockIdx.x * 256 + tid] = ssum2[tid] + ssum2[tid + 256];
}

// Exclusive prefix over 16 chunks/head, in place. grid = 128.
__global__ void k_scan() {
    int bh = blockIdx.x >> 2, c = blockIdx.x & 3;
    int d0 = c * 16;
    int m = threadIdx.x;
    float run[16];
    #pragma unroll
    for (int k = 0; k < 16; k++) run[k] = 0.f;
    for (int j = 0; j < 16; j++) {
        float* p = &g_kv[((size_t)(bh*16 + j) * 256 + m) * 64 + d0];
        #pragma unroll
        for (int k4 = 0; k4 < 4; k4++) {
            float4 v = *(float4*)&p[k4*4];
            *(float4*)&p[k4*4] = make_float4(run[k4*4], run[k4*4+1], run[k4*4+2], run[k4*4+3]);
            run[k4*4] += v.x; run[k4*4+1] += v.y; run[k4*4+2] += v.z; run[k4*4+3] += v.w;
        }
    }
    if (c == 0) {
        float rs = 0.f;
        for (int j = 0; j < 16; j++) {
            size_t idx = (size_t)(bh*16 + j) * 256 + m;
            float v = g_s[idx]; g_s[idx] = rs; rs += v;
        }
    }
}

// ---------------------------------------------------------------------------
// Attention block. 512 thr, 16 warps (2x8). grid = 512. smem 204.8KB.
// ---------------------------------------------------------------------------
__global__ __launch_bounds__(512) void k_attn(const float* __restrict__ v,
                                              float* __restrict__ out) {
    extern __shared__ float sm[];
    // Phase 2 layout
    float2* Ahl = (float2*)sm;              // [128][132] f2 = 33792 floats
    float2* vhl = (float2*)(sm + 33792);    // [128][68] f2 (persists from phase 1)
    // Phase 1 aliases inside [0, 33792)
    float2* qphl = (float2*)sm;             // [128][36] f2 = 9216 floats
    float2* kphl = (float2*)(sm + 9216);    // [128][36] f2
    float2* pshl = (float2*)(sm + 18432);   // [32][68] f2 = 4352 floats
    __shared__ float Ss_s[32];
    __shared__ float den1[128], den2[128];

    int tid = threadIdx.x, lane = tid & 31, wid = tid >> 5;
    int g = lane >> 2, t = lane & 3;
    int wr = wid >> 3, wc = wid & 7;   // 2 x 8 warps
    int bh = blockIdx.x >> 4, j = blockIdx.x & 15;
    int b = bh >> 3, h = bh & 7;
    size_t rowbase = (size_t)(b * 2048 + j * 128) * 8 + h;

    float CA[4][2][4];   // A: rows wr*64+mt*16, cols wc*16+nt*8
    float CN[4][4];      // NP/AV: rows wr*64+mt*16, cols wc*8
    #pragma unroll
    for (int mt = 0; mt < 4; mt++) {
        #pragma unroll
        for (int nt = 0; nt < 2; nt++)
            #pragma unroll
            for (int i = 0; i < 4; i++) CA[mt][nt][i] = 0.f;
        #pragma unroll
        for (int i = 0; i < 4; i++) CN[mt][i] = 0.f;
    }
    float denq = 0.f;

    #pragma unroll 1
    for (int kc = 0; kc < 8; kc++) {
        __syncthreads();
        for (int idx = tid; idx < 1024; idx += 512) {   // qp chunk: split
            int r = idx >> 3, k4 = idx & 7;
            st_split4(&qphl[r*36 + k4*4],
                      *(const float4*)&g_qp[(rowbase + (size_t)r * 8) * 256 + kc*32 + k4*4]);
        }
        for (int idx = tid; idx < 1024; idx += 512) {   // kp chunk: split
            int r = idx >> 3, k4 = idx & 7;
            st_split4(&kphl[r*36 + k4*4],
                      *(const float4*)&g_kp[(rowbase + (size_t)r * 8) * 256 + kc*32 + k4*4]);
        }
        for (int idx = tid; idx < 512; idx += 512) {    // Ps chunk: split
            int kk = idx >> 4, d4 = idx & 15;
            st_split4(&pshl[kk*68 + d4*4],
                      *(const float4*)&g_kv[(size_t)blockIdx.x * 16384 + (kc*32 + kk)*64 + d4*4]);
        }
        if (tid < 32) Ss_s[tid] = g_s[blockIdx.x * 256 + kc*32 + tid];
        if (kc == 0) {
            for (int idx = tid; idx < 2048; idx += 512) {   // V: split (lives above aliases)
                int u = idx >> 4, d4 = idx & 15;
                st_split4(&vhl[u*68 + d4*4],
                          *(const float4*)&v[(rowbase + (size_t)u * 8) * 64 + d4*4]);
            }
        }
        __syncthreads();

        #pragma unroll
        for (int k0 = 0; k0 < 32; k0 += 8) {
            FA a[4]; FB bA[2], bP;
            #pragma unroll
            for (int mt = 0; mt < 4; mt++) lda2(a[mt], qphl, 36, wr*64 + mt*16, k0, g, t);
            #pragma unroll
            for (int nt = 0; nt < 2; nt++) ldb2_nk(bA[nt], kphl, 36, wc*16 + nt*8, k0, g, t);
            ldb2_kn(bP, pshl, 68, k0, wc*8, g, t);
            #pragma unroll
            for (int mt = 0; mt < 4; mt++) {
                #pragma unroll
                for (int nt = 0; nt < 2; nt++)
                    if (wc*16 + nt*8 <= wr*64 + mt*16 + 15)   // skip fully-masked tiles
                        mma3(CA[mt][nt], a[mt], bA[nt]);
                mma3(CN[mt], a[mt], bP);
            }
        }
        if (tid < 128) {
            #pragma unroll
            for (int kk = 0; kk < 32; kk++) {
                float2 hl = qphl[tid*36 + kk];
                denq += (hl.x + hl.y) * Ss_s[kk];
            }
        }
    }
    __syncthreads();   // phase-1 smem dead; alias Ahl

    #pragma unroll
    for (int mt = 0; mt < 4; mt++)
        #pragma unroll
        for (int nt = 0; nt < 2; nt++) {
            int r = wr*64 + mt*16 + g, c = wc*16 + nt*8 + 2*t;
            float a0 = (c   <= r)   ? CA[mt][nt][0] : 0.f;
            float a1 = (c+1 <= r)   ? CA[mt][nt][1] : 0.f;
            float a2 = (c   <= r+8) ? CA[mt][nt][2] : 0.f;
            float a3 = (c+1 <= r+8) ? CA[mt][nt][3] : 0.f;
            st_split2(&Ahl[r*132 + c],     a0, a1);   // exactly the 2 owned cols
            st_split2(&Ahl[(r+8)*132 + c], a2, a3);
        }
    if (tid < 128) den1[tid] = denq;
    __syncthreads();

    if (tid < 128) {
        float rs = 0.f;
        #pragma unroll
        for (int u = 0; u < 128; u++) {
            float2 hl = Ahl[tid*132 + u];
            rs += hl.x + hl.y;
        }
        den2[tid] = rs;
    }

    int kmax = wr*64 + 64;
    #pragma unroll 1
    for (int k0 = 0; k0 < kmax; k0 += 8) {
        FA a[4]; FB bV;
        #pragma unroll
        for (int mt = 0; mt < 4; mt++) lda2(a[mt], Ahl, 132, wr*64 + mt*16, k0, g, t);
        ldb2_kn(bV, vhl, 68, k0, wc*8, g, t);
        #pragma unroll
        for (int mt = 0; mt < 4; mt++)
            if (k0 <= wr*64 + mt*16 + 15)
                mma3(CN[mt], a[mt], bV);
    }
    __syncthreads();

    #pragma unroll
    for (int mt = 0; mt < 4; mt++) {
        int r = wr*64 + mt*16 + g, c = wc*8 + 2*t;
        float den = den1[r] + den2[r];
        den += (fabsf(den) <= 1e-6f) ? 2e-6f : 0.f;
        float inv = 1.f / den;
        *(float2*)&out[(rowbase + (size_t)r * 8) * 64 + c] =
            make_float2(CN[mt][0] * inv, CN[mt][1] * inv);
        float den8 = den1[r+8] + den2[r+8];
        den8 += (fabsf(den8) <= 1e-6f) ? 2e-6f : 0.f;
        float inv8 = 1.f / den8;
        *(float2*)&out[(rowbase + (size_t)(r+8) * 8) * 64 + c] =
            make_float2(CN[mt][2] * inv8, CN[mt][3] * inv8);
    }
}

extern "C" void kernel_launch(void* const* d_in, const int* in_sizes, int n_in,
                              void* d_out, int out_size) {
    const float* q    = (const float*)d_in[0];
    const float* k    = (const float*)d_in[1];
    const float* v    = (const float*)d_in[2];
    const float* proj = (const float*)d_in[3];
    float* out = (float*)d_out;
    (void)in_sizes; (void)n_in; (void)out_size;

    const int SMF = 174080;   // k_feat:  43520 floats
    const int SMK = 83968;    // k_kvblk: 20992 floats
    const int SMA = 204800;   // k_attn:  51200 floats
    cudaFuncSetAttribute(k_feat,  cudaFuncAttributeMaxDynamicSharedMemorySize, SMF);
    cudaFuncSetAttribute(k_kvblk, cudaFuncAttributeMaxDynamicSharedMemorySize, SMK);
    cudaFuncSetAttribute(k_attn,  cudaFuncAttributeMaxDynamicSharedMemorySize, SMA);

    k_init<<<1, 32>>>();
    k_feat<<<1024, 512, SMF>>>(q, proj, 1);
    k_feat<<<1024, 512, SMF>>>(k, proj, 0);
    k_kvblk<<<512, 512, SMK>>>(v);
    k_scan<<<128, 256>>>();
    k_attn<<<512, 512, SMA>>>(v, out);
}